// round 2
// baseline (speedup 1.0000x reference)
#include <cuda_runtime.h>
#include <cstdint>

#define CLA_L     16384
#define CLA_HID   512
#define CLA_QKVN  1536
#define CLA_CS    256

__device__ int   g_order[CLA_L];
__device__ float g_qkv[(size_t)CLA_L * CLA_QKVN];
__device__ float g_attn[(size_t)CLA_L * CLA_HID];

__device__ __forceinline__ unsigned f2tf32(float f) {
    unsigned u;
    asm("cvt.rna.tf32.f32 %0, %1;" : "=r"(u) : "f"(f));
    return u;
}

__device__ __forceinline__ void mma_tf32(float* c, const unsigned* a,
                                         unsigned b0, unsigned b1) {
    asm volatile(
        "mma.sync.aligned.m16n8k8.row.col.f32.tf32.tf32.f32 "
        "{%0,%1,%2,%3}, {%4,%5,%6,%7}, {%8,%9}, {%0,%1,%2,%3};\n"
        : "+f"(c[0]), "+f"(c[1]), "+f"(c[2]), "+f"(c[3])
        : "r"(a[0]), "r"(a[1]), "r"(a[2]), "r"(a[3]), "r"(b0), "r"(b1));
}

// FMA-only 2^y, y <= 0, clamped; rel err ~2e-6
__device__ __forceinline__ float fexp2(float y) {
    y = fmaxf(y, -126.0f);
    float n = rintf(y);
    float f = y - n;
    float p = 1.33335581e-3f;
    p = fmaf(p, f, 9.61812910e-3f);
    p = fmaf(p, f, 5.55041087e-2f);
    p = fmaf(p, f, 2.40226507e-1f);
    p = fmaf(p, f, 6.93147180e-1f);
    p = fmaf(p, f, 1.0f);
    return __int_as_float(((int)n + 127) << 23) * p;
}

// ------------------- stable counting-sort order (1 warp / cluster) ---------
__global__ void build_order_k(const void* labv) {
    const int lane = threadIdx.x;
    const long long cc = (long long)blockIdx.x;
    const int* a32 = (const int*)labv;
    const long long* a64 = (const long long*)labv;
    int any = 0;
    for (int i = 2 * lane + 1; i < CLA_L; i += 64) any |= a32[i];
    const bool is64 = (__ballot_sync(0xffffffffu, any != 0) == 0);

    int lt = 0;
    for (int i = lane; i < CLA_L; i += 32) {
        long long v = is64 ? a64[i] : (long long)a32[i];
        lt += (v < cc) ? 1 : 0;
    }
    #pragma unroll
    for (int o = 16; o; o >>= 1) lt += __shfl_xor_sync(0xffffffffu, lt, o);
    int pos = lt;
    for (int base = 0; base < CLA_L; base += 32) {
        long long v = is64 ? a64[base + lane] : (long long)a32[base + lane];
        unsigned m = __ballot_sync(0xffffffffu, v == cc);
        if (v == cc) g_order[pos + __popc(m & ((1u << lane) - 1))] = base + lane;
        pos += __popc(m);
    }
}

// ------------------- tf32 GEMM, BM=BN=128, BK=32, 256 thr ------------------
// MODE 0: C=g_qkv[M,1536] = x[g_order[r]] @ W_qkv + b
// MODE 1: C=out[M,512]    = g_attn @ W_out + b + x[g_order[r]]
template <int MODE>
__global__ void __launch_bounds__(256, 2)
gemm_tf32_k(const float* __restrict__ A, const float* __restrict__ B,
            const float* __restrict__ bias, const float* __restrict__ residX,
            float* __restrict__ Cp, int N) {
    __shared__ unsigned As[128][36];
    __shared__ unsigned Bs[32][132];

    const int tid = threadIdx.x, lane = tid & 31, wid = tid >> 5;
    const int gid = lane >> 2, tig = lane & 3;
    const int wm = wid >> 2, wn = wid & 3;
    const int bm = blockIdx.y << 7, bn = blockIdx.x << 7;

    const float* Asrc = (MODE == 0) ? A : g_attn;
    float* C = (MODE == 0) ? g_qkv : Cp;

    float acc[4][4][4];
    #pragma unroll
    for (int i = 0; i < 4; i++)
        #pragma unroll
        for (int j = 0; j < 4; j++)
            #pragma unroll
            for (int r = 0; r < 4; r++) acc[i][j][r] = 0.f;

    int arow[4];
    #pragma unroll
    for (int i = 0; i < 4; i++) {
        int r = (tid + (i << 8)) >> 3;
        arow[i] = (MODE == 0) ? g_order[bm + r] : (bm + r);
    }

    for (int k0 = 0; k0 < CLA_HID; k0 += 32) {
        #pragma unroll
        for (int i = 0; i < 4; i++) {
            int lin = tid + (i << 8);
            int r = lin >> 3, c4 = (lin & 7) << 2;
            float4 v = *reinterpret_cast<const float4*>(
                Asrc + (size_t)arow[i] * CLA_HID + k0 + c4);
            As[r][c4] = f2tf32(v.x);   As[r][c4 + 1] = f2tf32(v.y);
            As[r][c4 + 2] = f2tf32(v.z); As[r][c4 + 3] = f2tf32(v.w);
        }
        #pragma unroll
        for (int i = 0; i < 4; i++) {
            int lin = tid + (i << 8);
            int r = lin >> 5, c4 = (lin & 31) << 2;
            float4 v = *reinterpret_cast<const float4*>(
                B + (size_t)(k0 + r) * N + bn + c4);
            Bs[r][c4] = f2tf32(v.x);   Bs[r][c4 + 1] = f2tf32(v.y);
            Bs[r][c4 + 2] = f2tf32(v.z); Bs[r][c4 + 3] = f2tf32(v.w);
        }
        __syncthreads();
        #pragma unroll
        for (int kk = 0; kk < 4; kk++) {
            const int ks = kk << 3;
            unsigned a[4][4], b[4][2];
            #pragma unroll
            for (int mt = 0; mt < 4; mt++) {
                int rb = wm * 64 + mt * 16;
                a[mt][0] = As[rb + gid][ks + tig];
                a[mt][1] = As[rb + gid + 8][ks + tig];
                a[mt][2] = As[rb + gid][ks + tig + 4];
                a[mt][3] = As[rb + gid + 8][ks + tig + 4];
            }
            #pragma unroll
            for (int nt = 0; nt < 4; nt++) {
                int cb = wn * 32 + nt * 8 + gid;
                b[nt][0] = Bs[ks + tig][cb];
                b[nt][1] = Bs[ks + tig + 4][cb];
            }
            #pragma unroll
            for (int mt = 0; mt < 4; mt++)
                #pragma unroll
                for (int nt = 0; nt < 4; nt++)
                    mma_tf32(acc[mt][nt], a[mt], b[nt][0], b[nt][1]);
        }
        __syncthreads();
    }

    #pragma unroll
    for (int mt = 0; mt < 4; mt++)
        #pragma unroll
        for (int hf = 0; hf < 2; hf++) {
            int row = bm + wm * 64 + mt * 16 + hf * 8 + gid;
            int xrow = (MODE == 1) ? g_order[row] : 0;
            #pragma unroll
            for (int nt = 0; nt < 4; nt++) {
                int col = bn + wn * 32 + nt * 8 + tig * 2;
                float v0 = acc[mt][nt][hf * 2] + bias[col];
                float v1 = acc[mt][nt][hf * 2 + 1] + bias[col + 1];
                if (MODE == 1) {
                    v0 += residX[(size_t)xrow * CLA_HID + col];
                    v1 += residX[(size_t)xrow * CLA_HID + col + 1];
                }
                C[(size_t)row * N + col] = v0;
                C[(size_t)row * N + col + 1] = v1;
            }
        }
}

// ------------------- attention: 1 CTA per (head, cluster) ------------------
#define ATTN_SMEM_BYTES ((2 * 256 * 68 + 8 * 32 * 36) * 4)

__global__ void __launch_bounds__(256, 1) attn_k() {
    extern __shared__ unsigned sm[];
    unsigned* Ks = sm;                 // [256][68]
    unsigned* Vs = sm + 256 * 68;      // [256][68]
    unsigned* Ps = sm + 2 * 256 * 68;  // 8 x [32][36]

    const int tid = threadIdx.x, lane = tid & 31, wid = tid >> 5;
    const int gid = lane >> 2, tig = lane & 3;
    const int h = blockIdx.x & 7, c = blockIdx.x >> 3;
    const size_t rowbase = (size_t)c << 8;
    const int qoff = h << 6, koff = CLA_HID + qoff, voff = 2 * CLA_HID + qoff;
    const float Cl = 0.18033688011112042f;  // log2(e)/8

    #pragma unroll
    for (int i = 0; i < 16; i++) {
        int lin = tid + (i << 8);
        int r = lin >> 4, c4 = (lin & 15) << 2;
        const float* rp = g_qkv + (rowbase + r) * CLA_QKVN;
        float4 kv = *reinterpret_cast<const float4*>(rp + koff + c4);
        float4 vv = *reinterpret_cast<const float4*>(rp + voff + c4);
        Ks[r * 68 + c4] = f2tf32(kv.x);     Ks[r * 68 + c4 + 1] = f2tf32(kv.y);
        Ks[r * 68 + c4 + 2] = f2tf32(kv.z); Ks[r * 68 + c4 + 3] = f2tf32(kv.w);
        Vs[r * 68 + c4] = f2tf32(vv.x);     Vs[r * 68 + c4 + 1] = f2tf32(vv.y);
        Vs[r * 68 + c4 + 2] = f2tf32(vv.z); Vs[r * 68 + c4 + 3] = f2tf32(vv.w);
    }

    unsigned qa[2][8][4];
    {
        const float* qb = g_qkv + rowbase * CLA_QKVN + qoff;
        int qr0 = wid * 32;
        #pragma unroll
        for (int mt = 0; mt < 2; mt++)
            #pragma unroll
            for (int ks = 0; ks < 8; ks++) {
                size_t r0 = (size_t)(qr0 + mt * 16 + gid) * CLA_QKVN;
                size_t r1 = r0 + 8 * CLA_QKVN;
                qa[mt][ks][0] = f2tf32(qb[r0 + ks * 8 + tig]);
                qa[mt][ks][1] = f2tf32(qb[r1 + ks * 8 + tig]);
                qa[mt][ks][2] = f2tf32(qb[r0 + ks * 8 + tig + 4]);
                qa[mt][ks][3] = f2tf32(qb[r1 + ks * 8 + tig + 4]);
            }
    }
    __syncthreads();

    float Oa[2][8][4];
    float mrow[2][2], srow[2][2];
    #pragma unroll
    for (int mt = 0; mt < 2; mt++) {
        mrow[mt][0] = mrow[mt][1] = -1e30f;
        srow[mt][0] = srow[mt][1] = 0.f;
        #pragma unroll
        for (int n = 0; n < 8; n++)
            #pragma unroll
            for (int r = 0; r < 4; r++) Oa[mt][n][r] = 0.f;
    }
    unsigned* Pw = Ps + wid * 32 * 36;

    for (int kt = 0; kt < 8; kt++) {
        float Sa[2][4][4];
        #pragma unroll
        for (int mt = 0; mt < 2; mt++)
            #pragma unroll
            for (int nt = 0; nt < 4; nt++)
                #pragma unroll
                for (int r = 0; r < 4; r++) Sa[mt][nt][r] = 0.f;

        #pragma unroll
        for (int ks = 0; ks < 8; ks++) {
            unsigned b[4][2];
            #pragma unroll
            for (int nt = 0; nt < 4; nt++) {
                int kr = kt * 32 + nt * 8 + gid;
                b[nt][0] = Ks[kr * 68 + ks * 8 + tig];
                b[nt][1] = Ks[kr * 68 + ks * 8 + tig + 4];
            }
            #pragma unroll
            for (int mt = 0; mt < 2; mt++)
                #pragma unroll
                for (int nt = 0; nt < 4; nt++)
                    mma_tf32(Sa[mt][nt], qa[mt][ks], b[nt][0], b[nt][1]);
        }

        #pragma unroll
        for (int mt = 0; mt < 2; mt++) {
            float mx0 = -1e30f, mx1 = -1e30f;
            #pragma unroll
            for (int nt = 0; nt < 4; nt++) {
                mx0 = fmaxf(mx0, fmaxf(Sa[mt][nt][0], Sa[mt][nt][1]));
                mx1 = fmaxf(mx1, fmaxf(Sa[mt][nt][2], Sa[mt][nt][3]));
            }
            mx0 = fmaxf(mx0, __shfl_xor_sync(0xffffffffu, mx0, 1));
            mx0 = fmaxf(mx0, __shfl_xor_sync(0xffffffffu, mx0, 2));
            mx1 = fmaxf(mx1, __shfl_xor_sync(0xffffffffu, mx1, 1));
            mx1 = fmaxf(mx1, __shfl_xor_sync(0xffffffffu, mx1, 2));
            float nm0 = fmaxf(mrow[mt][0], mx0), nm1 = fmaxf(mrow[mt][1], mx1);
            float al0 = fexp2((mrow[mt][0] - nm0) * Cl);
            float al1 = fexp2((mrow[mt][1] - nm1) * Cl);
            mrow[mt][0] = nm0; mrow[mt][1] = nm1;
            float ps0 = 0.f, ps1 = 0.f;
            #pragma unroll
            for (int nt = 0; nt < 4; nt++) {
                float p0 = fexp2((Sa[mt][nt][0] - nm0) * Cl);
                float p1 = fexp2((Sa[mt][nt][1] - nm0) * Cl);
                float p2 = fexp2((Sa[mt][nt][2] - nm1) * Cl);
                float p3 = fexp2((Sa[mt][nt][3] - nm1) * Cl);
                ps0 += p0 + p1; ps1 += p2 + p3;
                int r0 = mt * 16 + gid, col = nt * 8 + tig * 2;
                Pw[r0 * 36 + col] = f2tf32(p0);
                Pw[r0 * 36 + col + 1] = f2tf32(p1);
                Pw[(r0 + 8) * 36 + col] = f2tf32(p2);
                Pw[(r0 + 8) * 36 + col + 1] = f2tf32(p3);
            }
            ps0 += __shfl_xor_sync(0xffffffffu, ps0, 1);
            ps0 += __shfl_xor_sync(0xffffffffu, ps0, 2);
            ps1 += __shfl_xor_sync(0xffffffffu, ps1, 1);
            ps1 += __shfl_xor_sync(0xffffffffu, ps1, 2);
            srow[mt][0] = srow[mt][0] * al0 + ps0;
            srow[mt][1] = srow[mt][1] * al1 + ps1;
            #pragma unroll
            for (int n = 0; n < 8; n++) {
                Oa[mt][n][0] *= al0; Oa[mt][n][1] *= al0;
                Oa[mt][n][2] *= al1; Oa[mt][n][3] *= al1;
            }
        }
        __syncwarp();

        #pragma unroll
        for (int ks = 0; ks < 4; ks++) {
            unsigned a[2][4];
            #pragma unroll
            for (int mt = 0; mt < 2; mt++) {
                int r0 = mt * 16;
                a[mt][0] = Pw[(r0 + gid) * 36 + ks * 8 + tig];
                a[mt][1] = Pw[(r0 + gid + 8) * 36 + ks * 8 + tig];
                a[mt][2] = Pw[(r0 + gid) * 36 + ks * 8 + tig + 4];
                a[mt][3] = Pw[(r0 + gid + 8) * 36 + ks * 8 + tig + 4];
            }
            int vr = kt * 32 + ks * 8;
            #pragma unroll
            for (int n = 0; n < 8; n++) {
                unsigned b0 = Vs[(vr + tig) * 68 + n * 8 + gid];
                unsigned b1 = Vs[(vr + tig + 4) * 68 + n * 8 + gid];
                #pragma unroll
                for (int mt = 0; mt < 2; mt++) mma_tf32(Oa[mt][n], a[mt], b0, b1);
            }
        }
        __syncwarp();
    }

    #pragma unroll
    for (int mt = 0; mt < 2; mt++) {
        float inv0 = 1.f / srow[mt][0], inv1 = 1.f / srow[mt][1];
        size_t r0 = rowbase + wid * 32 + mt * 16 + gid;
        #pragma unroll
        for (int n = 0; n < 8; n++) {
            int col = qoff + n * 8 + tig * 2;
            g_attn[r0 * CLA_HID + col] = Oa[mt][n][0] * inv0;
            g_attn[r0 * CLA_HID + col + 1] = Oa[mt][n][1] * inv0;
            g_attn[(r0 + 8) * CLA_HID + col] = Oa[mt][n][2] * inv1;
            g_attn[(r0 + 8) * CLA_HID + col + 1] = Oa[mt][n][3] * inv1;
        }
    }
}

extern "C" void kernel_launch(void* const* d_in, const int* in_sizes, int n_in,
                              void* d_out, int out_size) {
    const float* x = (const float*)d_in[0];
    const void* lab = d_in[1];
    const float* Wqkv = (const float*)d_in[2];
    const float* bqkv = (const float*)d_in[3];
    const float* Wout = (const float*)d_in[4];
    const float* bout = (const float*)d_in[5];
    float* out = (float*)d_out;

    cudaFuncSetAttribute(attn_k, cudaFuncAttributeMaxDynamicSharedMemorySize,
                         ATTN_SMEM_BYTES);

    build_order_k<<<64, 32>>>(lab);
    gemm_tf32_k<0><<<dim3(12, 128), 256>>>(x, Wqkv, bqkv, nullptr, nullptr,
                                           CLA_QKVN);
    attn_k<<<512, 256, ATTN_SMEM_BYTES>>>();
    gemm_tf32_k<1><<<dim3(4, 128), 256>>>(nullptr, Wout, bout, x, out, CLA_HID);
}

// round 3
// speedup vs baseline: 1.5680x; 1.5680x over previous
#include <cuda_runtime.h>
#include <cuda_bf16.h>
#include <cstdint>

#define CLA_L     16384
#define CLA_HID   512
#define CLA_QKVN  1536

__device__ int           g_order[CLA_L];
__device__ __nv_bfloat16 g_xb[(size_t)CLA_L * CLA_HID];
__device__ __nv_bfloat16 g_wqkvt[(size_t)CLA_QKVN * CLA_HID];
__device__ __nv_bfloat16 g_woutt[(size_t)CLA_HID * CLA_HID];
__device__ __nv_bfloat16 g_qkvb[(size_t)CLA_L * CLA_QKVN];
__device__ __nv_bfloat16 g_attnb[(size_t)CLA_L * CLA_HID];

__device__ __forceinline__ uint32_t s2u(const void* p) {
    return (uint32_t)__cvta_generic_to_shared(p);
}
__device__ __forceinline__ void cp_async16(uint32_t dst, const void* src) {
    asm volatile("cp.async.cg.shared.global [%0], [%1], 16;\n" ::"r"(dst), "l"(src));
}
__device__ __forceinline__ void cp_commit() {
    asm volatile("cp.async.commit_group;\n");
}
template <int N> __device__ __forceinline__ void cp_wait() {
    asm volatile("cp.async.wait_group %0;\n" ::"n"(N));
}
__device__ __forceinline__ void ldsm_x4(unsigned* r, uint32_t a) {
    asm volatile("ldmatrix.sync.aligned.m8n8.x4.shared.b16 {%0,%1,%2,%3}, [%4];\n"
                 : "=r"(r[0]), "=r"(r[1]), "=r"(r[2]), "=r"(r[3]) : "r"(a));
}
__device__ __forceinline__ void ldsm_x2(unsigned& r0, unsigned& r1, uint32_t a) {
    asm volatile("ldmatrix.sync.aligned.m8n8.x2.shared.b16 {%0,%1}, [%2];\n"
                 : "=r"(r0), "=r"(r1) : "r"(a));
}
__device__ __forceinline__ void mma_bf16(float* c, const unsigned* a,
                                         unsigned b0, unsigned b1) {
    asm volatile(
        "mma.sync.aligned.m16n8k16.row.col.f32.bf16.bf16.f32 "
        "{%0,%1,%2,%3},{%4,%5,%6,%7},{%8,%9},{%0,%1,%2,%3};\n"
        : "+f"(c[0]), "+f"(c[1]), "+f"(c[2]), "+f"(c[3])
        : "r"(a[0]), "r"(a[1]), "r"(a[2]), "r"(a[3]), "r"(b0), "r"(b1));
}
__device__ __forceinline__ void mma_tf32(float* c, const unsigned* a,
                                         unsigned b0, unsigned b1) {
    asm volatile(
        "mma.sync.aligned.m16n8k8.row.col.f32.tf32.tf32.f32 "
        "{%0,%1,%2,%3},{%4,%5,%6,%7},{%8,%9},{%0,%1,%2,%3};\n"
        : "+f"(c[0]), "+f"(c[1]), "+f"(c[2]), "+f"(c[3])
        : "r"(a[0]), "r"(a[1]), "r"(a[2]), "r"(a[3]), "r"(b0), "r"(b1));
}
__device__ __forceinline__ unsigned f2tf32(float f) {
    unsigned u;
    asm("cvt.rna.tf32.f32 %0, %1;" : "=r"(u) : "f"(f));
    return u;
}
// FMA-only 2^y (no MUFU), rel err ~2e-6
__device__ __forceinline__ float fexp2(float y) {
    y = fmaxf(y, -126.0f);
    float n = rintf(y);
    float f = y - n;
    float p = 1.33335581e-3f;
    p = fmaf(p, f, 9.61812910e-3f);
    p = fmaf(p, f, 5.55041087e-2f);
    p = fmaf(p, f, 2.40226507e-1f);
    p = fmaf(p, f, 6.93147180e-1f);
    p = fmaf(p, f, 1.0f);
    return __int_as_float(((int)n + 127) << 23) * p;
}

// ------------------- prep kernels ------------------------------------------
__global__ void build_order_k(const void* labv) {
    const int lane = threadIdx.x;
    const long long cc = (long long)blockIdx.x;
    const int* a32 = (const int*)labv;
    const long long* a64 = (const long long*)labv;
    int any = 0;
    for (int i = 2 * lane + 1; i < CLA_L; i += 64) any |= a32[i];
    const bool is64 = (__ballot_sync(0xffffffffu, any != 0) == 0);
    int lt = 0;
    for (int i = lane; i < CLA_L; i += 32) {
        long long v = is64 ? a64[i] : (long long)a32[i];
        lt += (v < cc) ? 1 : 0;
    }
    #pragma unroll
    for (int o = 16; o; o >>= 1) lt += __shfl_xor_sync(0xffffffffu, lt, o);
    int pos = lt;
    for (int base = 0; base < CLA_L; base += 32) {
        long long v = is64 ? a64[base + lane] : (long long)a32[base + lane];
        unsigned m = __ballot_sync(0xffffffffu, v == cc);
        if (v == cc) g_order[pos + __popc(m & ((1u << lane) - 1))] = base + lane;
        pos += __popc(m);
    }
}

__global__ void cvt_x_k(const float* __restrict__ x) {
    size_t i = ((size_t)blockIdx.x * 256 + threadIdx.x) * 4;
    float4 v = *reinterpret_cast<const float4*>(x + i);
    *reinterpret_cast<__nv_bfloat162*>(g_xb + i) = __floats2bfloat162_rn(v.x, v.y);
    *reinterpret_cast<__nv_bfloat162*>(g_xb + i + 2) = __floats2bfloat162_rn(v.z, v.w);
}

// W [K][N] fp32 -> Wt [N][K] bf16
__global__ void transpose_cvt_k(const float* __restrict__ W,
                                __nv_bfloat16* __restrict__ Wt, int K, int N) {
    __shared__ float tile[32][33];
    int bx = blockIdx.x * 32, by = blockIdx.y * 32;
    int tx = threadIdx.x & 31, ty = threadIdx.x >> 5;
    #pragma unroll
    for (int i = 0; i < 32; i += 8)
        tile[ty + i][tx] = W[(size_t)(by + ty + i) * N + bx + tx];
    __syncthreads();
    #pragma unroll
    for (int i = 0; i < 32; i += 8)
        Wt[(size_t)(bx + ty + i) * K + by + tx] = __float2bfloat16(tile[tx][ty + i]);
}

// ------------------- bf16 GEMM, BM=BN=128, BK=32, cp.async x2 buf ----------
// MODE 0: g_qkvb[m][1536] = bf16( x[g_order[m]] @ Wqkv + b )
// MODE 1: out  [m][512]   = g_attnb @ Wout + b + x[g_order[m]]   (fp32)
template <int MODE>
__global__ void __launch_bounds__(256, 2)
gemm_bf16_k(const __nv_bfloat16* __restrict__ Bt, const float* __restrict__ bias,
            const float* __restrict__ residX, float* __restrict__ outF, int N) {
    __shared__ __align__(16) unsigned char smbuf[2][16384];  // [buf][A 8K | B 8K]
    const int tid = threadIdx.x, lane = tid & 31, wid = tid >> 5;
    const int gid = lane >> 2, tig = lane & 3;
    const int wm = wid >> 2, wn = wid & 3;
    const int bm = blockIdx.y << 7, bn = blockIdx.x << 7;
    const uint32_t smbase = s2u(smbuf);

    // fill coords: rows r0f, r0f+64; 16B chunk cf
    const int r0f = tid >> 2, cf = tid & 3;
    const __nv_bfloat16* arow0;
    const __nv_bfloat16* arow1;
    if (MODE == 0) {
        arow0 = g_xb + (size_t)g_order[bm + r0f] * CLA_HID;
        arow1 = g_xb + (size_t)g_order[bm + r0f + 64] * CLA_HID;
    } else {
        arow0 = g_attnb + (size_t)(bm + r0f) * CLA_HID;
        arow1 = g_attnb + (size_t)(bm + r0f + 64) * CLA_HID;
    }
    const __nv_bfloat16* brow0 = Bt + (size_t)(bn + r0f) * CLA_HID;
    const __nv_bfloat16* brow1 = Bt + (size_t)(bn + r0f + 64) * CLA_HID;
    const uint32_t dA = r0f * 64 + ((cf ^ ((r0f >> 1) & 3)) << 4);

    float acc[4][4][4];
    #pragma unroll
    for (int i = 0; i < 4; i++)
        #pragma unroll
        for (int j = 0; j < 4; j++)
            #pragma unroll
            for (int r = 0; r < 4; r++) acc[i][j][r] = 0.f;

    // ldmatrix lane coords
    const int aro = ((lane >> 3) & 1) * 8 + (lane & 7);
    const int ach = lane >> 4;
    const int bro = lane & 7;
    const int bch = (lane >> 3) & 1;
    const int sA = (aro >> 1) & 3, sB = (bro >> 1) & 3;
    uint32_t arb[4], brb[4];
    #pragma unroll
    for (int mt = 0; mt < 4; mt++) arb[mt] = (wm * 64 + mt * 16 + aro) * 64;
    #pragma unroll
    for (int nt = 0; nt < 4; nt++) brb[nt] = (wn * 32 + nt * 8 + bro) * 64 + 8192;

    #define FILL(t, b)                                                          \
        do {                                                                    \
            int kb = (t) * 64;                                                  \
            uint32_t ab = smbase + (b) * 16384;                                 \
            cp_async16(ab + dA, (const char*)arow0 + kb + cf * 16);             \
            cp_async16(ab + dA + 4096, (const char*)arow1 + kb + cf * 16);      \
            cp_async16(ab + 8192 + dA, (const char*)brow0 + kb + cf * 16);      \
            cp_async16(ab + 8192 + dA + 4096, (const char*)brow1 + kb + cf * 16);\
            cp_commit();                                                        \
        } while (0)

    FILL(0, 0);
    for (int t = 0; t < 16; t++) {
        if (t + 1 < 16) {
            FILL(t + 1, (t + 1) & 1);
            cp_wait<1>();
        } else {
            cp_wait<0>();
        }
        __syncthreads();
        uint32_t base = smbase + (t & 1) * 16384;
        #pragma unroll
        for (int kk = 0; kk < 2; kk++) {
            unsigned a[4][4], b[4][2];
            #pragma unroll
            for (int mt = 0; mt < 4; mt++)
                ldsm_x4(a[mt], base + arb[mt] + (((kk * 2 + ach) ^ sA) << 4));
            #pragma unroll
            for (int nt = 0; nt < 4; nt++)
                ldsm_x2(b[nt][0], b[nt][1],
                        base + brb[nt] + (((kk * 2 + bch) ^ sB) << 4));
            #pragma unroll
            for (int mt = 0; mt < 4; mt++)
                #pragma unroll
                for (int nt = 0; nt < 4; nt++)
                    mma_bf16(acc[mt][nt], a[mt], b[nt][0], b[nt][1]);
        }
        __syncthreads();
    }
    #undef FILL

    #pragma unroll
    for (int mt = 0; mt < 4; mt++)
        #pragma unroll
        for (int hf = 0; hf < 2; hf++) {
            int row = bm + wm * 64 + mt * 16 + hf * 8 + gid;
            int xrow = (MODE == 1) ? g_order[row] : 0;
            #pragma unroll
            for (int nt = 0; nt < 4; nt++) {
                int col = bn + wn * 32 + nt * 8 + tig * 2;
                float v0 = acc[mt][nt][hf * 2] + bias[col];
                float v1 = acc[mt][nt][hf * 2 + 1] + bias[col + 1];
                if (MODE == 0) {
                    *reinterpret_cast<__nv_bfloat162*>(
                        g_qkvb + (size_t)row * CLA_QKVN + col) =
                        __floats2bfloat162_rn(v0, v1);
                } else {
                    v0 += residX[(size_t)xrow * CLA_HID + col];
                    v1 += residX[(size_t)xrow * CLA_HID + col + 1];
                    outF[(size_t)row * CLA_HID + col] = v0;
                    outF[(size_t)row * CLA_HID + col + 1] = v1;
                }
            }
        }
}

// ------------------- attention: 1 CTA per (head, cluster), tf32 mma --------
#define ATTN_SMEM_BYTES ((2 * 256 * 68 + 8 * 32 * 36) * 4)

__global__ void __launch_bounds__(256, 1) attn_k() {
    extern __shared__ unsigned sm[];
    unsigned* Ks = sm;
    unsigned* Vs = sm + 256 * 68;
    unsigned* Ps = sm + 2 * 256 * 68;

    const int tid = threadIdx.x, lane = tid & 31, wid = tid >> 5;
    const int gid = lane >> 2, tig = lane & 3;
    const int h = blockIdx.x & 7, c = blockIdx.x >> 3;
    const size_t rowbase = (size_t)c << 8;
    const int qoff = h << 6, koff = CLA_HID + qoff, voff = 2 * CLA_HID + qoff;
    const float Cl = 0.18033688011112042f;  // log2(e)/8

    #pragma unroll
    for (int i = 0; i < 16; i++) {
        int lin = tid + (i << 8);
        int r = lin >> 4, c4 = (lin & 15) << 2;
        const __nv_bfloat16* rp = g_qkvb + (rowbase + r) * CLA_QKVN;
        float2 k0 = __bfloat1622float2(*(const __nv_bfloat162*)(rp + koff + c4));
        float2 k1 = __bfloat1622float2(*(const __nv_bfloat162*)(rp + koff + c4 + 2));
        float2 v0 = __bfloat1622float2(*(const __nv_bfloat162*)(rp + voff + c4));
        float2 v1 = __bfloat1622float2(*(const __nv_bfloat162*)(rp + voff + c4 + 2));
        Ks[r * 68 + c4] = __float_as_uint(k0.x);
        Ks[r * 68 + c4 + 1] = __float_as_uint(k0.y);
        Ks[r * 68 + c4 + 2] = __float_as_uint(k1.x);
        Ks[r * 68 + c4 + 3] = __float_as_uint(k1.y);
        Vs[r * 68 + c4] = __float_as_uint(v0.x);
        Vs[r * 68 + c4 + 1] = __float_as_uint(v0.y);
        Vs[r * 68 + c4 + 2] = __float_as_uint(v1.x);
        Vs[r * 68 + c4 + 3] = __float_as_uint(v1.y);
    }

    unsigned qa[2][8][4];
    {
        const __nv_bfloat16* qb = g_qkvb + rowbase * CLA_QKVN + qoff;
        int qr0 = wid * 32;
        #pragma unroll
        for (int mt = 0; mt < 2; mt++)
            #pragma unroll
            for (int ks = 0; ks < 8; ks++) {
                size_t r0 = (size_t)(qr0 + mt * 16 + gid) * CLA_QKVN;
                size_t r1 = r0 + 8 * CLA_QKVN;
                qa[mt][ks][0] = __float_as_uint(__bfloat162float(qb[r0 + ks * 8 + tig]));
                qa[mt][ks][1] = __float_as_uint(__bfloat162float(qb[r1 + ks * 8 + tig]));
                qa[mt][ks][2] = __float_as_uint(__bfloat162float(qb[r0 + ks * 8 + tig + 4]));
                qa[mt][ks][3] = __float_as_uint(__bfloat162float(qb[r1 + ks * 8 + tig + 4]));
            }
    }
    __syncthreads();

    float Oa[2][8][4];
    float mrow[2][2], srow[2][2];
    #pragma unroll
    for (int mt = 0; mt < 2; mt++) {
        mrow[mt][0] = mrow[mt][1] = -1e30f;
        srow[mt][0] = srow[mt][1] = 0.f;
        #pragma unroll
        for (int n = 0; n < 8; n++)
            #pragma unroll
            for (int r = 0; r < 4; r++) Oa[mt][n][r] = 0.f;
    }
    unsigned* Pw = Ps + wid * 32 * 36;

    for (int kt = 0; kt < 8; kt++) {
        float Sa[2][4][4];
        #pragma unroll
        for (int mt = 0; mt < 2; mt++)
            #pragma unroll
            for (int nt = 0; nt < 4; nt++)
                #pragma unroll
                for (int r = 0; r < 4; r++) Sa[mt][nt][r] = 0.f;

        #pragma unroll
        for (int ks = 0; ks < 8; ks++) {
            unsigned b[4][2];
            #pragma unroll
            for (int nt = 0; nt < 4; nt++) {
                int kr = kt * 32 + nt * 8 + gid;
                b[nt][0] = Ks[kr * 68 + ks * 8 + tig];
                b[nt][1] = Ks[kr * 68 + ks * 8 + tig + 4];
            }
            #pragma unroll
            for (int mt = 0; mt < 2; mt++)
                #pragma unroll
                for (int nt = 0; nt < 4; nt++)
                    mma_tf32(Sa[mt][nt], qa[mt][ks], b[nt][0], b[nt][1]);
        }

        #pragma unroll
        for (int mt = 0; mt < 2; mt++) {
            float mx0 = -1e30f, mx1 = -1e30f;
            #pragma unroll
            for (int nt = 0; nt < 4; nt++) {
                mx0 = fmaxf(mx0, fmaxf(Sa[mt][nt][0], Sa[mt][nt][1]));
                mx1 = fmaxf(mx1, fmaxf(Sa[mt][nt][2], Sa[mt][nt][3]));
            }
            mx0 = fmaxf(mx0, __shfl_xor_sync(0xffffffffu, mx0, 1));
            mx0 = fmaxf(mx0, __shfl_xor_sync(0xffffffffu, mx0, 2));
            mx1 = fmaxf(mx1, __shfl_xor_sync(0xffffffffu, mx1, 1));
            mx1 = fmaxf(mx1, __shfl_xor_sync(0xffffffffu, mx1, 2));
            float nm0 = fmaxf(mrow[mt][0], mx0), nm1 = fmaxf(mrow[mt][1], mx1);
            float al0 = fexp2((mrow[mt][0] - nm0) * Cl);
            float al1 = fexp2((mrow[mt][1] - nm1) * Cl);
            mrow[mt][0] = nm0; mrow[mt][1] = nm1;
            float ps0 = 0.f, ps1 = 0.f;
            #pragma unroll
            for (int nt = 0; nt < 4; nt++) {
                float p0 = fexp2((Sa[mt][nt][0] - nm0) * Cl);
                float p1 = fexp2((Sa[mt][nt][1] - nm0) * Cl);
                float p2 = fexp2((Sa[mt][nt][2] - nm1) * Cl);
                float p3 = fexp2((Sa[mt][nt][3] - nm1) * Cl);
                ps0 += p0 + p1; ps1 += p2 + p3;
                int r0 = mt * 16 + gid, col = nt * 8 + tig * 2;
                Pw[r0 * 36 + col] = f2tf32(p0);
                Pw[r0 * 36 + col + 1] = f2tf32(p1);
                Pw[(r0 + 8) * 36 + col] = f2tf32(p2);
                Pw[(r0 + 8) * 36 + col + 1] = f2tf32(p3);
            }
            ps0 += __shfl_xor_sync(0xffffffffu, ps0, 1);
            ps0 += __shfl_xor_sync(0xffffffffu, ps0, 2);
            ps1 += __shfl_xor_sync(0xffffffffu, ps1, 1);
            ps1 += __shfl_xor_sync(0xffffffffu, ps1, 2);
            srow[mt][0] = srow[mt][0] * al0 + ps0;
            srow[mt][1] = srow[mt][1] * al1 + ps1;
            #pragma unroll
            for (int n = 0; n < 8; n++) {
                Oa[mt][n][0] *= al0; Oa[mt][n][1] *= al0;
                Oa[mt][n][2] *= al1; Oa[mt][n][3] *= al1;
            }
        }
        __syncwarp();

        #pragma unroll
        for (int ks = 0; ks < 4; ks++) {
            unsigned a[2][4];
            #pragma unroll
            for (int mt = 0; mt < 2; mt++) {
                int r0 = mt * 16;
                a[mt][0] = Pw[(r0 + gid) * 36 + ks * 8 + tig];
                a[mt][1] = Pw[(r0 + gid + 8) * 36 + ks * 8 + tig];
                a[mt][2] = Pw[(r0 + gid) * 36 + ks * 8 + tig + 4];
                a[mt][3] = Pw[(r0 + gid + 8) * 36 + ks * 8 + tig + 4];
            }
            int vr = kt * 32 + ks * 8;
            #pragma unroll
            for (int n = 0; n < 8; n++) {
                unsigned b0 = Vs[(vr + tig) * 68 + n * 8 + gid];
                unsigned b1 = Vs[(vr + tig + 4) * 68 + n * 8 + gid];
                #pragma unroll
                for (int mt = 0; mt < 2; mt++) mma_tf32(Oa[mt][n], a[mt], b0, b1);
            }
        }
        __syncwarp();
    }

    #pragma unroll
    for (int mt = 0; mt < 2; mt++) {
        float inv0 = 1.f / srow[mt][0], inv1 = 1.f / srow[mt][1];
        size_t r0 = rowbase + wid * 32 + mt * 16 + gid;
        #pragma unroll
        for (int n = 0; n < 8; n++) {
            int col = qoff + n * 8 + tig * 2;
            *reinterpret_cast<__nv_bfloat162*>(g_attnb + r0 * CLA_HID + col) =
                __floats2bfloat162_rn(Oa[mt][n][0] * inv0, Oa[mt][n][1] * inv0);
            *reinterpret_cast<__nv_bfloat162*>(g_attnb + (r0 + 8) * CLA_HID + col) =
                __floats2bfloat162_rn(Oa[mt][n][2] * inv1, Oa[mt][n][3] * inv1);
        }
    }
}

extern "C" void kernel_launch(void* const* d_in, const int* in_sizes, int n_in,
                              void* d_out, int out_size) {
    const float* x = (const float*)d_in[0];
    const void* lab = d_in[1];
    const float* Wqkv = (const float*)d_in[2];
    const float* bqkv = (const float*)d_in[3];
    const float* Wout = (const float*)d_in[4];
    const float* bout = (const float*)d_in[5];
    float* out = (float*)d_out;

    cudaFuncSetAttribute(attn_k, cudaFuncAttributeMaxDynamicSharedMemorySize,
                         ATTN_SMEM_BYTES);

    __nv_bfloat16* wqkvt; cudaGetSymbolAddress((void**)&wqkvt, g_wqkvt);
    __nv_bfloat16* woutt; cudaGetSymbolAddress((void**)&woutt, g_woutt);

    build_order_k<<<64, 32>>>(lab);
    cvt_x_k<<<(CLA_L * CLA_HID) / (256 * 4), 256>>>(x);
    transpose_cvt_k<<<dim3(CLA_QKVN / 32, CLA_HID / 32), 256>>>(Wqkv, wqkvt,
                                                                CLA_HID, CLA_QKVN);
    transpose_cvt_k<<<dim3(CLA_HID / 32, CLA_HID / 32), 256>>>(Wout, woutt,
                                                               CLA_HID, CLA_HID);
    gemm_bf16_k<0><<<dim3(12, 128), 256>>>(wqkvt, bqkv, nullptr, nullptr, CLA_QKVN);
    attn_k<<<512, 256, ATTN_SMEM_BYTES>>>();
    gemm_bf16_k<1><<<dim3(4, 128), 256>>>(woutt, bout, x, out, CLA_HID);
}